// round 1
// baseline (speedup 1.0000x reference)
#include <cuda_runtime.h>

// Problem constants
#define DM    100
#define NSDK  2048
#define ROWS  1024        // SZ_B * L
#define NBLK  32768       // SZ_B * NS
#define DI_   400
#define KSPLIT 8

// Scratch (device globals — no allocation)
__device__ float g_qkv[3u * 2097152u];      // Q,K,V each [32768][64]
__device__ float g_att[ROWS * NSDK];        // attention output, row-major [1024][2048]
__device__ float g_part[KSPLIT * ROWS * DM];// fc split-K partials
__device__ float g_ln1[ROWS * DM];          // LN1 output

// ---------------------------------------------------------------------------
// K1: QKV projection GEMM (1024x2048, K=100) + per-proj affine, writes into
// attention layout: buf[batch*4096 + ns*64 + l*32 + dk]
// grid (32 coltiles, 16 rowtiles, 3 projections), 256 threads, 64x64 tile
// ---------------------------------------------------------------------------
__global__ void qkv_kernel(const float* __restrict__ edges,
                           const float* __restrict__ wq, const float* __restrict__ bq,
                           const float* __restrict__ wk, const float* __restrict__ bk,
                           const float* __restrict__ wv, const float* __restrict__ bv,
                           const float* __restrict__ qcw, const float* __restrict__ qcb,
                           const float* __restrict__ kcw, const float* __restrict__ kcb,
                           const float* __restrict__ vcw, const float* __restrict__ vcb)
{
    __shared__ float As[50 * 68];   // [k][row], padded
    __shared__ float Bs[50 * 68];   // [k][col], padded

    const int t  = threadIdx.x;
    const int tx = t & 15;          // col group (4 cols each)
    const int ty = t >> 4;          // row group (4 rows each)
    const int col0 = blockIdx.x * 64;
    const int row0 = blockIdx.y * 64;
    const int p    = blockIdx.z;

    const float* W;  const float* bias;  const float* cw;  const float* cb;
    float* out;
    if (p == 0)      { W = wq; bias = bq; cw = qcw; cb = qcb; out = g_qkv; }
    else if (p == 1) { W = wk; bias = bk; cw = kcw; cb = kcb; out = g_qkv + 2097152; }
    else             { W = wv; bias = bv; cw = vcw; cb = vcb; out = g_qkv + 2u * 2097152u; }

    float acc[4][4] = {};

    for (int half = 0; half < 2; half++) {
        const int kbase = half * 50;
        __syncthreads();
        // load 64 rows x 50 k for both A (edges) and B (weight)
        for (int idx = t; idx < 3200; idx += 256) {
            int r = idx / 50;
            int k = idx - r * 50;
            As[k * 68 + r] = edges[(row0 + r) * DM + kbase + k];
            Bs[k * 68 + r] = W[(col0 + r) * DM + kbase + k];
        }
        __syncthreads();

        for (int k = 0; k < 50; k++) {
            float4 a4 = *(const float4*)&As[k * 68 + ty * 4];
            float4 b4 = *(const float4*)&Bs[k * 68 + tx * 4];
            float a[4] = {a4.x, a4.y, a4.z, a4.w};
            float b[4] = {b4.x, b4.y, b4.z, b4.w};
            #pragma unroll
            for (int i = 0; i < 4; i++)
                #pragma unroll
                for (int j = 0; j < 4; j++)
                    acc[i][j] = fmaf(a[i], b[j], acc[i][j]);
        }
    }

    const float scale = *cw;
    const float shift = *cb;
    const int c = col0 + tx * 4;        // 4-aligned, never crosses a 32-boundary
    const int ns = c >> 5;
    const int dk = c & 31;
    float4 bb = *(const float4*)&bias[c];

    #pragma unroll
    for (int i = 0; i < 4; i++) {
        int row   = row0 + ty * 4 + i;
        int batch = row >> 1;
        int l     = row & 1;
        float4 v;
        v.x = fmaf(scale, acc[i][0] + bb.x, shift);
        v.y = fmaf(scale, acc[i][1] + bb.y, shift);
        v.z = fmaf(scale, acc[i][2] + bb.z, shift);
        v.w = fmaf(scale, acc[i][3] + bb.w, shift);
        *(float4*)&out[batch * 4096 + ns * 64 + l * 32 + dk] = v;
    }
}

// ---------------------------------------------------------------------------
// K2: attention. 4 sub-blocks (b values) per 256-thread block; thread = (h,w).
// 34-way softmax (32 cross-H with diag mask + 2 in-W), writes g_att row-major.
// ---------------------------------------------------------------------------
__global__ void attn_kernel()
{
    __shared__ float sq[4][64], sk[4][64], sv[4][64];
    const int t   = threadIdx.x;
    const int sub = t >> 6;
    const int lt  = t & 63;
    const int b   = blockIdx.x * 4 + sub;
    const int batch = b >> 6;
    const int ns    = b & 63;
    const int base  = batch * 4096 + ns * 64;

    sq[sub][lt] = g_qkv[base + lt];
    sk[sub][lt] = g_qkv[2097152u + base + lt];
    sv[sub][lt] = g_qkv[2u * 2097152u + base + lt];
    __syncthreads();

    const int h = lt >> 1;
    const int w = lt & 1;
    const float q = sq[sub][lt];
    const float* Kv = sk[sub];
    const float* Vv = sv[sub];

    const float ew0 = q * Kv[h * 2 + 0];
    const float ew1 = q * Kv[h * 2 + 1];
    float m = fmaxf(ew0, ew1);
    #pragma unroll
    for (int g = 0; g < 32; g++) {
        float e = (g == h) ? -1e30f : q * Kv[g * 2 + w];
        m = fmaxf(m, e);
    }
    float Z   = __expf(ew0 - m) + __expf(ew1 - m);
    float acc = __expf(ew0 - m) * Vv[h * 2 + 0] + __expf(ew1 - m) * Vv[h * 2 + 1];
    #pragma unroll
    for (int g = 0; g < 32; g++) {
        float e = (g == h) ? -1e30f : q * Kv[g * 2 + w];
        float pz = __expf(e - m);
        Z   += pz;
        acc  = fmaf(pz, Vv[g * 2 + w], acc);
    }
    const float o = acc / Z;
    const int l  = lt >> 5;
    const int dk = lt & 31;
    g_att[(batch * 2 + l) * NSDK + ns * 32 + dk] = o;
}

// ---------------------------------------------------------------------------
// K3a: fc GEMM split-K partials. out[row][c] = sum_k att[row][k]*fcw[c][k]
// grid (2 coltiles[64], 16 rowtiles[64], 8 ksplits[256]); 256 threads
// ---------------------------------------------------------------------------
__global__ void fc_partial_kernel(const float* __restrict__ fcw)
{
    __shared__ float As[32 * 68];   // [kk][row]
    __shared__ float Bs[32 * 68];   // [kk][col]
    const int t  = threadIdx.x;
    const int tx = t & 15;
    const int ty = t >> 4;
    const int c0   = blockIdx.x * 64;
    const int row0 = blockIdx.y * 64;
    const int ks   = blockIdx.z;

    float acc[4][4] = {};

    for (int sub = 0; sub < 8; sub++) {
        const int k0 = ks * 256 + sub * 32;
        __syncthreads();
        for (int idx = t; idx < 2048; idx += 256) {
            int r  = idx >> 5;
            int kk = idx & 31;
            As[kk * 68 + r] = g_att[(row0 + r) * NSDK + k0 + kk];
            int cc = c0 + r;
            Bs[kk * 68 + r] = (cc < DM) ? fcw[cc * NSDK + k0 + kk] : 0.0f;
        }
        __syncthreads();
        for (int kk = 0; kk < 32; kk++) {
            float4 a4 = *(const float4*)&As[kk * 68 + ty * 4];
            float4 b4 = *(const float4*)&Bs[kk * 68 + tx * 4];
            float a[4] = {a4.x, a4.y, a4.z, a4.w};
            float b[4] = {b4.x, b4.y, b4.z, b4.w};
            #pragma unroll
            for (int i = 0; i < 4; i++)
                #pragma unroll
                for (int j = 0; j < 4; j++)
                    acc[i][j] = fmaf(a[i], b[j], acc[i][j]);
        }
    }

    const int c = c0 + tx * 4;
    if (c < DM) {
        #pragma unroll
        for (int i = 0; i < 4; i++) {
            int row = row0 + ty * 4 + i;
            float4 v = make_float4(acc[i][0], acc[i][1], acc[i][2], acc[i][3]);
            *(float4*)&g_part[ks * (ROWS * DM) + row * DM + c] = v;
        }
    }
}

// ---------------------------------------------------------------------------
// K3b: reduce partials + bias + residual + LayerNorm1. One block per row.
// ---------------------------------------------------------------------------
__global__ void ln1_kernel(const float* __restrict__ edges,
                           const float* __restrict__ fcb,
                           const float* __restrict__ g1,
                           const float* __restrict__ b1)
{
    __shared__ float red[128];
    const int row = blockIdx.x;
    const int t   = threadIdx.x;

    float x = 0.0f;
    if (t < DM) {
        x = fcb[t] + edges[row * DM + t];
        #pragma unroll
        for (int s = 0; s < KSPLIT; s++)
            x += g_part[s * (ROWS * DM) + row * DM + t];
    }

    red[t] = (t < DM) ? x : 0.0f;
    __syncthreads();
    for (int off = 64; off > 0; off >>= 1) {
        if (t < off) red[t] += red[t + off];
        __syncthreads();
    }
    const float mean = red[0] * (1.0f / DM);
    __syncthreads();

    float d = (t < DM) ? (x - mean) : 0.0f;
    red[t] = d * d;
    __syncthreads();
    for (int off = 64; off > 0; off >>= 1) {
        if (t < off) red[t] += red[t + off];
        __syncthreads();
    }
    const float var = red[0] * (1.0f / DM);
    const float inv = rsqrtf(var + 1e-5f);

    if (t < DM)
        g_ln1[row * DM + t] = d * inv * g1[t] + b1[t];
}

// ---------------------------------------------------------------------------
// K4: fused MLP (100->400 relu ->100) + residual + LayerNorm2 -> d_out.
// 8 rows per block, 128 blocks, 256 threads.
// ---------------------------------------------------------------------------
__global__ void mlp_kernel(const float* __restrict__ w1, const float* __restrict__ b1,
                           const float* __restrict__ w2, const float* __restrict__ b2,
                           const float* __restrict__ g2, const float* __restrict__ bb2,
                           float* __restrict__ outp)
{
    __shared__ float xs[8][100];
    __shared__ float hs[8][400];
    __shared__ float ys[8][104];

    const int t    = threadIdx.x;
    const int row0 = blockIdx.x * 8;

    for (int idx = t; idx < 800; idx += 256) {
        int r = idx / DM;
        int c = idx - r * DM;
        xs[r][c] = g_ln1[(row0 + r) * DM + c];
    }
    __syncthreads();

    // h = relu(x @ w1^T + b1)
    for (int j = t; j < DI_; j += 256) {
        float acc[8] = {};
        for (int k = 0; k < DM; k++) {
            float wv = w1[j * DM + k];
            #pragma unroll
            for (int r = 0; r < 8; r++) acc[r] = fmaf(xs[r][k], wv, acc[r]);
        }
        float bj = b1[j];
        #pragma unroll
        for (int r = 0; r < 8; r++) hs[r][j] = fmaxf(acc[r] + bj, 0.0f);
    }
    __syncthreads();

    // y = h @ w2^T + b2 + residual(ln1)
    if (t < DM) {
        float acc[8] = {};
        for (int j = 0; j < DI_; j++) {
            float wv = w2[t * DI_ + j];
            #pragma unroll
            for (int r = 0; r < 8; r++) acc[r] = fmaf(hs[r][j], wv, acc[r]);
        }
        float bc = b2[t];
        #pragma unroll
        for (int r = 0; r < 8; r++) ys[r][t] = acc[r] + bc + xs[r][t];
    }
    __syncthreads();

    // LN2, one warp per row (8 warps, 8 rows)
    const int wid  = t >> 5;
    const int lane = t & 31;
    if (wid < 8) {
        const int r = wid;
        float s = 0.0f;
        for (int c = lane; c < DM; c += 32) s += ys[r][c];
        #pragma unroll
        for (int off = 16; off > 0; off >>= 1) s += __shfl_xor_sync(0xffffffffu, s, off);
        const float mean = s * (1.0f / DM);

        float v = 0.0f;
        for (int c = lane; c < DM; c += 32) {
            float d = ys[r][c] - mean;
            v = fmaf(d, d, v);
        }
        #pragma unroll
        for (int off = 16; off > 0; off >>= 1) v += __shfl_xor_sync(0xffffffffu, v, off);
        const float inv = rsqrtf(v * (1.0f / DM) + 1e-5f);

        for (int c = lane; c < DM; c += 32)
            outp[(row0 + r) * DM + c] = (ys[r][c] - mean) * inv * g2[c] + bb2[c];
    }
}

// ---------------------------------------------------------------------------
extern "C" void kernel_launch(void* const* d_in, const int* in_sizes, int n_in,
                              void* d_out, int out_size)
{
    (void)in_sizes; (void)n_in; (void)out_size;
    const float* edges = (const float*)d_in[0];
    const float* wq    = (const float*)d_in[1];
    const float* bq    = (const float*)d_in[2];
    const float* wk    = (const float*)d_in[3];
    const float* bk    = (const float*)d_in[4];
    const float* wv    = (const float*)d_in[5];
    const float* bv    = (const float*)d_in[6];
    const float* qcw   = (const float*)d_in[7];
    const float* qcb   = (const float*)d_in[8];
    const float* kcw   = (const float*)d_in[9];
    const float* kcb   = (const float*)d_in[10];
    const float* vcw   = (const float*)d_in[11];
    const float* vcb   = (const float*)d_in[12];
    const float* fcw   = (const float*)d_in[13];
    const float* fcb   = (const float*)d_in[14];
    const float* ln1g  = (const float*)d_in[15];
    const float* ln1b  = (const float*)d_in[16];
    const float* w1w   = (const float*)d_in[17];
    const float* w1b   = (const float*)d_in[18];
    const float* w2w   = (const float*)d_in[19];
    const float* w2b   = (const float*)d_in[20];
    const float* ln2g  = (const float*)d_in[21];
    const float* ln2b  = (const float*)d_in[22];

    qkv_kernel<<<dim3(32, 16, 3), 256>>>(edges, wq, bq, wk, bk, wv, bv,
                                         qcw, qcb, kcw, kcb, vcw, vcb);
    attn_kernel<<<NBLK / 4, 256>>>();
    fc_partial_kernel<<<dim3(2, 16, KSPLIT), 256>>>(fcw);
    ln1_kernel<<<ROWS, 128>>>(edges, fcb, ln1g, ln1b);
    mlp_kernel<<<ROWS / 8, 256>>>(w1w, w1b, w2w, w2b, ln2g, ln2b, (float*)d_out);
}

// round 2
// speedup vs baseline: 1.1618x; 1.1618x over previous
#include <cuda_runtime.h>

// Problem constants
#define DM    100
#define NSDK  2048
#define ROWS  1024        // SZ_B * L
#define NBLK  32768       // SZ_B * NS
#define DI_   400
#define KSPLIT 16
#define PART_STRIDE (ROWS * DM)

// Scratch (device globals — no allocation)
__device__ float g_qkv[3u * 2097152u];        // Q,K,V each [32768][64]
__device__ float g_att[ROWS * NSDK];          // attention output [1024][2048]
__device__ float g_part[KSPLIT * PART_STRIDE];// fc split-K partials
__device__ float g_ln1[ROWS * DM];            // LN1 output

// ---------------------------------------------------------------------------
// tf32 helpers
// ---------------------------------------------------------------------------
__device__ __forceinline__ unsigned f2tf(float v) {
    unsigned r;
    asm("cvt.rna.tf32.f32 %0, %1;" : "=r"(r) : "f"(v));
    return r;
}

__device__ __forceinline__ void mma_tf32(float c[4],
                                         unsigned a0, unsigned a1, unsigned a2, unsigned a3,
                                         unsigned b0, unsigned b1) {
    asm("mma.sync.aligned.m16n8k8.row.col.f32.tf32.tf32.f32 "
        "{%0,%1,%2,%3},{%4,%5,%6,%7},{%8,%9},{%0,%1,%2,%3};"
        : "+f"(c[0]), "+f"(c[1]), "+f"(c[2]), "+f"(c[3])
        : "r"(a0), "r"(a1), "r"(a2), "r"(a3), "r"(b0), "r"(b1));
}

// ---------------------------------------------------------------------------
// K1: QKV projection GEMM (1024 x 6144, K=100) on tensor cores (tf32).
// Block tile 64(M) x 128(N), 128 threads (4 warps, 2x2), warp tile 32x64.
// Epilogue: affine (scale,shift) + bias, write to attention layout.
// grid (48, 16)
// ---------------------------------------------------------------------------
__global__ __launch_bounds__(128) void qkv_tc(const float* __restrict__ edges,
                           const float* __restrict__ wq, const float* __restrict__ bq,
                           const float* __restrict__ wk, const float* __restrict__ bk,
                           const float* __restrict__ wv, const float* __restrict__ bv,
                           const float* __restrict__ qcw, const float* __restrict__ qcb,
                           const float* __restrict__ kcw, const float* __restrict__ kcb,
                           const float* __restrict__ vcw, const float* __restrict__ vcb)
{
    __shared__ unsigned As[32 * 72];    // [kk][m], pitch 72 (conflict-free frags)
    __shared__ unsigned Bs[32 * 136];   // [kk][n], pitch 136

    const int t    = threadIdx.x;
    const int lane = t & 31;
    const int wid  = t >> 5;
    const int tig  = lane & 3;          // threadID_in_group
    const int gid  = lane >> 2;         // groupID

    const int col0 = blockIdx.x * 128;  // global col in [0,6144)
    const int row0 = blockIdx.y * 64;
    const int p    = col0 >> 11;        // projection 0/1/2
    const int lc0  = col0 & 2047;       // col within projection

    const float* W;  const float* bias;  const float* cw;  const float* cb;
    float* out;
    if (p == 0)      { W = wq; bias = bq; cw = qcw; cb = qcb; out = g_qkv; }
    else if (p == 1) { W = wk; bias = bk; cw = kcw; cb = kcb; out = g_qkv + 2097152u; }
    else             { W = wv; bias = bv; cw = vcw; cb = vcb; out = g_qkv + 2u * 2097152u; }

    const int wm0 = (wid >> 1) * 32;
    const int wn0 = (wid & 1) * 64;

    float acc[2][8][4] = {};

    for (int kc = 0; kc < 4; kc++) {
        const int kb = kc * 32;
        __syncthreads();
        #pragma unroll
        for (int idx = t; idx < 2048; idx += 128) {
            int kk = idx & 31, m = idx >> 5;
            int k  = kb + kk;
            As[kk * 72 + m] = f2tf(k < DM ? edges[(row0 + m) * DM + k] : 0.0f);
        }
        #pragma unroll
        for (int idx = t; idx < 4096; idx += 128) {
            int kk = idx & 31, n = idx >> 5;
            int k  = kb + kk;
            Bs[kk * 136 + n] = f2tf(k < DM ? W[(lc0 + n) * DM + k] : 0.0f);
        }
        __syncthreads();

        #pragma unroll
        for (int ks = 0; ks < 4; ks++) {
            const int k0 = ks * 8;
            unsigned a[2][4];
            #pragma unroll
            for (int i = 0; i < 2; i++) {
                int mb = wm0 + i * 16;
                a[i][0] = As[(k0 + tig) * 72 + mb + gid];
                a[i][1] = As[(k0 + tig) * 72 + mb + gid + 8];
                a[i][2] = As[(k0 + tig + 4) * 72 + mb + gid];
                a[i][3] = As[(k0 + tig + 4) * 72 + mb + gid + 8];
            }
            unsigned b[8][2];
            #pragma unroll
            for (int j = 0; j < 8; j++) {
                int nb = wn0 + j * 8;
                b[j][0] = Bs[(k0 + tig) * 136 + nb + gid];
                b[j][1] = Bs[(k0 + tig + 4) * 136 + nb + gid];
            }
            #pragma unroll
            for (int i = 0; i < 2; i++)
                #pragma unroll
                for (int j = 0; j < 8; j++)
                    mma_tf32(acc[i][j], a[i][0], a[i][1], a[i][2], a[i][3],
                             b[j][0], b[j][1]);
        }
    }

    const float scale = *cw;
    const float shift = *cb;

    #pragma unroll
    for (int i = 0; i < 2; i++) {
        #pragma unroll
        for (int j = 0; j < 8; j++) {
            const int colg = lc0 + wn0 + j * 8 + 2 * tig;   // even
            const float b0v = bias[colg];
            const float b1v = bias[colg + 1];
            const int ns = colg >> 5;
            const int dk = colg & 31;

            int r0 = row0 + wm0 + i * 16 + gid;
            {
                int batch = r0 >> 1, l = r0 & 1;
                float2 v;
                v.x = fmaf(scale, acc[i][j][0] + b0v, shift);
                v.y = fmaf(scale, acc[i][j][1] + b1v, shift);
                *(float2*)&out[batch * 4096 + ns * 64 + l * 32 + dk] = v;
            }
            int r1 = r0 + 8;
            {
                int batch = r1 >> 1, l = r1 & 1;
                float2 v;
                v.x = fmaf(scale, acc[i][j][2] + b0v, shift);
                v.y = fmaf(scale, acc[i][j][3] + b1v, shift);
                *(float2*)&out[batch * 4096 + ns * 64 + l * 32 + dk] = v;
            }
        }
    }
}

// ---------------------------------------------------------------------------
// K2: attention. 4 sub-blocks per 256-thread block; thread = (h,w).
// 34-way softmax, writes g_att row-major. (MUFU-bound, near floor.)
// ---------------------------------------------------------------------------
__global__ void attn_kernel()
{
    __shared__ float sq[4][64], sk[4][64], sv[4][64];
    const int t   = threadIdx.x;
    const int sub = t >> 6;
    const int lt  = t & 63;
    const int b   = blockIdx.x * 4 + sub;
    const int batch = b >> 6;
    const int ns    = b & 63;
    const int base  = batch * 4096 + ns * 64;

    sq[sub][lt] = g_qkv[base + lt];
    sk[sub][lt] = g_qkv[2097152u + base + lt];
    sv[sub][lt] = g_qkv[2u * 2097152u + base + lt];
    __syncthreads();

    const int h = lt >> 1;
    const int w = lt & 1;
    const float q = sq[sub][lt];
    const float* Kv = sk[sub];
    const float* Vv = sv[sub];

    const float ew0 = q * Kv[h * 2 + 0];
    const float ew1 = q * Kv[h * 2 + 1];
    float m = fmaxf(ew0, ew1);
    #pragma unroll
    for (int g = 0; g < 32; g++) {
        float e = (g == h) ? -1e30f : q * Kv[g * 2 + w];
        m = fmaxf(m, e);
    }
    float p0 = __expf(ew0 - m);
    float p1 = __expf(ew1 - m);
    float Z   = p0 + p1;
    float acc = p0 * Vv[h * 2 + 0] + p1 * Vv[h * 2 + 1];
    #pragma unroll
    for (int g = 0; g < 32; g++) {
        float e = (g == h) ? -1e30f : q * Kv[g * 2 + w];
        float pz = __expf(e - m);
        Z   += pz;
        acc  = fmaf(pz, Vv[g * 2 + w], acc);
    }
    const float o = acc / Z;
    const int l  = lt >> 5;
    const int dk = lt & 31;
    g_att[(batch * 2 + l) * NSDK + ns * 32 + dk] = o;
}

// ---------------------------------------------------------------------------
// K3a: fc GEMM split-K partials on tensor cores (tf32).
// C[1024 x 100] = att[1024 x 2048] @ fcw[100 x 2048]^T
// Block tile 32(M) x 112(N pad), 128 threads (2x2 warps), warp tile 16x56.
// grid (32 mtiles, 16 ksplits); each ksplit covers K=128.
// ---------------------------------------------------------------------------
__global__ __launch_bounds__(128) void fc_tc(const float* __restrict__ fcw)
{
    __shared__ unsigned As[32 * 40];    // [kk][m], pitch 40
    __shared__ unsigned Bs[32 * 120];   // [kk][n], pitch 120

    const int t    = threadIdx.x;
    const int lane = t & 31;
    const int wid  = t >> 5;
    const int tig  = lane & 3;
    const int gid  = lane >> 2;

    const int row0 = blockIdx.x * 32;
    const int ks   = blockIdx.y;

    const int wm0 = (wid >> 1) * 16;
    const int wn0 = (wid & 1) * 56;

    float acc[7][4] = {};

    for (int kc = 0; kc < 4; kc++) {
        const int kb = ks * 128 + kc * 32;
        __syncthreads();
        #pragma unroll
        for (int idx = t; idx < 1024; idx += 128) {
            int kk = idx & 31, m = idx >> 5;
            As[kk * 40 + m] = f2tf(g_att[(row0 + m) * NSDK + kb + kk]);
        }
        #pragma unroll
        for (int idx = t; idx < 3584; idx += 128) {
            int kk = idx & 31, n = idx >> 5;
            Bs[kk * 120 + n] = f2tf(n < DM ? fcw[n * NSDK + kb + kk] : 0.0f);
        }
        __syncthreads();

        #pragma unroll
        for (int kss = 0; kss < 4; kss++) {
            const int k0 = kss * 8;
            unsigned a0 = As[(k0 + tig) * 40 + wm0 + gid];
            unsigned a1 = As[(k0 + tig) * 40 + wm0 + gid + 8];
            unsigned a2 = As[(k0 + tig + 4) * 40 + wm0 + gid];
            unsigned a3 = As[(k0 + tig + 4) * 40 + wm0 + gid + 8];
            unsigned b[7][2];
            #pragma unroll
            for (int j = 0; j < 7; j++) {
                int nb = wn0 + j * 8;
                b[j][0] = Bs[(k0 + tig) * 120 + nb + gid];
                b[j][1] = Bs[(k0 + tig + 4) * 120 + nb + gid];
            }
            #pragma unroll
            for (int j = 0; j < 7; j++)
                mma_tf32(acc[j], a0, a1, a2, a3, b[j][0], b[j][1]);
        }
    }

    #pragma unroll
    for (int j = 0; j < 7; j++) {
        const int col = wn0 + j * 8 + 2 * tig;   // even
        if (col < DM) {
            int r0 = row0 + wm0 + gid;
            *(float2*)&g_part[ks * PART_STRIDE + r0 * DM + col] =
                make_float2(acc[j][0], acc[j][1]);
            int r1 = r0 + 8;
            *(float2*)&g_part[ks * PART_STRIDE + r1 * DM + col] =
                make_float2(acc[j][2], acc[j][3]);
        }
    }
}

// ---------------------------------------------------------------------------
// K3b: reduce partials + bias + residual + LayerNorm1. Warp per row.
// grid 128, 256 threads (8 warps = 8 rows).
// ---------------------------------------------------------------------------
__global__ void ln1_kernel(const float* __restrict__ edges,
                           const float* __restrict__ fcb,
                           const float* __restrict__ g1,
                           const float* __restrict__ b1)
{
    const int wid  = threadIdx.x >> 5;
    const int lane = threadIdx.x & 31;
    const int row  = blockIdx.x * 8 + wid;

    float x[4];
    #pragma unroll
    for (int i = 0; i < 4; i++) {
        int c = lane + i * 32;
        float v = 0.0f;
        if (c < DM) {
            v = fcb[c] + edges[row * DM + c];
            #pragma unroll
            for (int s = 0; s < KSPLIT; s++)
                v += g_part[s * PART_STRIDE + row * DM + c];
        }
        x[i] = v;
    }

    float s = x[0] + x[1] + x[2] + x[3];
    #pragma unroll
    for (int off = 16; off > 0; off >>= 1) s += __shfl_xor_sync(0xffffffffu, s, off);
    const float mean = s * (1.0f / DM);

    float v2 = 0.0f;
    #pragma unroll
    for (int i = 0; i < 4; i++) {
        int c = lane + i * 32;
        if (c < DM) {
            float d = x[i] - mean;
            v2 = fmaf(d, d, v2);
        }
    }
    #pragma unroll
    for (int off = 16; off > 0; off >>= 1) v2 += __shfl_xor_sync(0xffffffffu, v2, off);
    const float inv = rsqrtf(v2 * (1.0f / DM) + 1e-5f);

    #pragma unroll
    for (int i = 0; i < 4; i++) {
        int c = lane + i * 32;
        if (c < DM)
            g_ln1[row * DM + c] = (x[i] - mean) * inv * g1[c] + b1[c];
    }
}

// ---------------------------------------------------------------------------
// K4: fused MLP (100->400 relu ->100) + residual + LayerNorm2 -> d_out.
// 8 rows per block, 128 blocks, 256 threads. Transposed smem: 2 LDS : 8 FMA.
// ---------------------------------------------------------------------------
__global__ void mlp_kernel(const float* __restrict__ w1, const float* __restrict__ b1,
                           const float* __restrict__ w2, const float* __restrict__ b2,
                           const float* __restrict__ g2, const float* __restrict__ bb2,
                           float* __restrict__ outp)
{
    __shared__ float xs[DM][8];          // [k][r]
    __shared__ float hs[DI_][8];         // [j][r]
    __shared__ float yh[2][8][104];      // layer-2 halves / final

    const int t    = threadIdx.x;
    const int row0 = blockIdx.x * 8;

    for (int idx = t; idx < DM * 8; idx += 256) {
        int c = idx >> 3, r = idx & 7;
        xs[c][r] = g_ln1[(row0 + r) * DM + c];
    }
    __syncthreads();

    // layer 1: h = relu(x @ w1^T + b1)
    for (int j = t; j < DI_; j += 256) {
        float acc[8] = {};
        #pragma unroll 4
        for (int k = 0; k < DM; k++) {
            float4 xa = *(const float4*)&xs[k][0];
            float4 xb = *(const float4*)&xs[k][4];
            float wv = w1[j * DM + k];
            acc[0] = fmaf(xa.x, wv, acc[0]);
            acc[1] = fmaf(xa.y, wv, acc[1]);
            acc[2] = fmaf(xa.z, wv, acc[2]);
            acc[3] = fmaf(xa.w, wv, acc[3]);
            acc[4] = fmaf(xb.x, wv, acc[4]);
            acc[5] = fmaf(xb.y, wv, acc[5]);
            acc[6] = fmaf(xb.z, wv, acc[6]);
            acc[7] = fmaf(xb.w, wv, acc[7]);
        }
        float bj = b1[j];
        float4 h0, h1;
        h0.x = fmaxf(acc[0] + bj, 0.0f);  h0.y = fmaxf(acc[1] + bj, 0.0f);
        h0.z = fmaxf(acc[2] + bj, 0.0f);  h0.w = fmaxf(acc[3] + bj, 0.0f);
        h1.x = fmaxf(acc[4] + bj, 0.0f);  h1.y = fmaxf(acc[5] + bj, 0.0f);
        h1.z = fmaxf(acc[6] + bj, 0.0f);  h1.w = fmaxf(acc[7] + bj, 0.0f);
        *(float4*)&hs[j][0] = h0;
        *(float4*)&hs[j][4] = h1;
    }
    __syncthreads();

    // layer 2: split K over 2 thread groups (threads 0..199)
    if (t < 200) {
        const int half = (t >= 100);
        const int c    = t - half * 100;
        const int j0   = half * 200;
        float acc[8] = {};
        #pragma unroll 4
        for (int jj = 0; jj < 200; jj++) {
            int j = j0 + jj;
            float4 ha = *(const float4*)&hs[j][0];
            float4 hb = *(const float4*)&hs[j][4];
            float wv = w2[c * DI_ + j];
            acc[0] = fmaf(ha.x, wv, acc[0]);
            acc[1] = fmaf(ha.y, wv, acc[1]);
            acc[2] = fmaf(ha.z, wv, acc[2]);
            acc[3] = fmaf(ha.w, wv, acc[3]);
            acc[4] = fmaf(hb.x, wv, acc[4]);
            acc[5] = fmaf(hb.y, wv, acc[5]);
            acc[6] = fmaf(hb.z, wv, acc[6]);
            acc[7] = fmaf(hb.w, wv, acc[7]);
        }
        #pragma unroll
        for (int r = 0; r < 8; r++) yh[half][r][c] = acc[r];
    }
    __syncthreads();

    // combine halves + bias + residual
    if (t < DM) {
        float bc = b2[t];
        #pragma unroll
        for (int r = 0; r < 8; r++)
            yh[0][r][t] += yh[1][r][t] + bc + xs[t][r];
    }
    __syncthreads();

    // LN2, warp per row
    const int wid  = t >> 5;
    const int lane = t & 31;
    {
        const int r = wid;
        float s = 0.0f;
        for (int c = lane; c < DM; c += 32) s += yh[0][r][c];
        #pragma unroll
        for (int off = 16; off > 0; off >>= 1) s += __shfl_xor_sync(0xffffffffu, s, off);
        const float mean = s * (1.0f / DM);

        float v = 0.0f;
        for (int c = lane; c < DM; c += 32) {
            float d = yh[0][r][c] - mean;
            v = fmaf(d, d, v);
        }
        #pragma unroll
        for (int off = 16; off > 0; off >>= 1) v += __shfl_xor_sync(0xffffffffu, v, off);
        const float inv = rsqrtf(v * (1.0f / DM) + 1e-5f);

        for (int c = lane; c < DM; c += 32)
            outp[(row0 + r) * DM + c] = (yh[0][r][c] - mean) * inv * g2[c] + bb2[c];
    }
}

// ---------------------------------------------------------------------------
extern "C" void kernel_launch(void* const* d_in, const int* in_sizes, int n_in,
                              void* d_out, int out_size)
{
    (void)in_sizes; (void)n_in; (void)out_size;
    const float* edges = (const float*)d_in[0];
    const float* wq    = (const float*)d_in[1];
    const float* bq    = (const float*)d_in[2];
    const float* wk    = (const float*)d_in[3];
    const float* bk    = (const float*)d_in[4];
    const float* wv    = (const float*)d_in[5];
    const float* bv    = (const float*)d_in[6];
    const float* qcw   = (const float*)d_in[7];
    const float* qcb   = (const float*)d_in[8];
    const float* kcw   = (const float*)d_in[9];
    const float* kcb   = (const float*)d_in[10];
    const float* vcw   = (const float*)d_in[11];
    const float* vcb   = (const float*)d_in[12];
    const float* fcw   = (const float*)d_in[13];
    const float* fcb   = (const float*)d_in[14];
    const float* ln1g  = (const float*)d_in[15];
    const float* ln1b  = (const float*)d_in[16];
    const float* w1w   = (const float*)d_in[17];
    const float* w1b   = (const float*)d_in[18];
    const float* w2w   = (const float*)d_in[19];
    const float* w2b   = (const float*)d_in[20];
    const float* ln2g  = (const float*)d_in[21];
    const float* ln2b  = (const float*)d_in[22];

    qkv_tc<<<dim3(48, 16), 128>>>(edges, wq, bq, wk, bk, wv, bv,
                                  qcw, qcb, kcw, kcb, vcw, vcb);
    attn_kernel<<<NBLK / 4, 256>>>();
    fc_tc<<<dim3(32, KSPLIT), 128>>>(fcw);
    ln1_kernel<<<ROWS / 8, 256>>>(edges, fcb, ln1g, ln1b);
    mlp_kernel<<<ROWS / 8, 256>>>(w1w, w1b, w2w, w2b, ln2g, ln2b, (float*)d_out);
}

// round 3
// speedup vs baseline: 1.2344x; 1.0625x over previous
#include <cuda_runtime.h>

// Problem constants
#define DM    100
#define NSDK  2048
#define ROWS  1024        // SZ_B * L
#define NBLK  32768       // SZ_B * NS
#define DI_   400
#define KSPLIT 4
#define PART_STRIDE (ROWS * DM)

// Scratch (device globals — no allocation)
__device__ float g_qkv[3u * 2097152u];        // Q,K,V each [32768][64]
__device__ float g_att[ROWS * NSDK];          // attention output [1024][2048]
__device__ float g_part[KSPLIT * PART_STRIDE];// fc split-K partials
__device__ float g_ln1[ROWS * DM];            // LN1 output
__device__ float g_h[ROWS * DI_];             // MLP hidden [1024][400]

// ---------------------------------------------------------------------------
// tf32 helpers
// ---------------------------------------------------------------------------
__device__ __forceinline__ unsigned f2tf(float v) {
    unsigned r;
    asm("cvt.rna.tf32.f32 %0, %1;" : "=r"(r) : "f"(v));
    return r;
}

__device__ __forceinline__ void mma_tf32(float c[4],
                                         unsigned a0, unsigned a1, unsigned a2, unsigned a3,
                                         unsigned b0, unsigned b1) {
    asm("mma.sync.aligned.m16n8k8.row.col.f32.tf32.tf32.f32 "
        "{%0,%1,%2,%3},{%4,%5,%6,%7},{%8,%9},{%0,%1,%2,%3};"
        : "+f"(c[0]), "+f"(c[1]), "+f"(c[2]), "+f"(c[3])
        : "r"(a0), "r"(a1), "r"(a2), "r"(a3), "r"(b0), "r"(b1));
}

// ---------------------------------------------------------------------------
// K1: QKV projection GEMM (1024 x 6144, K=100) on tensor cores (tf32).
// Block tile 64(M) x 128(N), 128 threads (4 warps, 2x2), warp tile 32x64.
// grid (48, 16)
// ---------------------------------------------------------------------------
__global__ __launch_bounds__(128) void qkv_tc(const float* __restrict__ edges,
                           const float* __restrict__ wq, const float* __restrict__ bq,
                           const float* __restrict__ wk, const float* __restrict__ bk,
                           const float* __restrict__ wv, const float* __restrict__ bv,
                           const float* __restrict__ qcw, const float* __restrict__ qcb,
                           const float* __restrict__ kcw, const float* __restrict__ kcb,
                           const float* __restrict__ vcw, const float* __restrict__ vcb)
{
    __shared__ unsigned As[32 * 72];
    __shared__ unsigned Bs[32 * 136];

    const int t    = threadIdx.x;
    const int lane = t & 31;
    const int wid  = t >> 5;
    const int tig  = lane & 3;
    const int gid  = lane >> 2;

    const int col0 = blockIdx.x * 128;
    const int row0 = blockIdx.y * 64;
    const int p    = col0 >> 11;
    const int lc0  = col0 & 2047;

    const float* W;  const float* bias;  const float* cw;  const float* cb;
    float* out;
    if (p == 0)      { W = wq; bias = bq; cw = qcw; cb = qcb; out = g_qkv; }
    else if (p == 1) { W = wk; bias = bk; cw = kcw; cb = kcb; out = g_qkv + 2097152u; }
    else             { W = wv; bias = bv; cw = vcw; cb = vcb; out = g_qkv + 2u * 2097152u; }

    const int wm0 = (wid >> 1) * 32;
    const int wn0 = (wid & 1) * 64;

    float acc[2][8][4] = {};

    for (int kc = 0; kc < 4; kc++) {
        const int kb = kc * 32;
        __syncthreads();
        #pragma unroll
        for (int idx = t; idx < 2048; idx += 128) {
            int kk = idx & 31, m = idx >> 5;
            int k  = kb + kk;
            As[kk * 72 + m] = f2tf(k < DM ? edges[(row0 + m) * DM + k] : 0.0f);
        }
        #pragma unroll
        for (int idx = t; idx < 4096; idx += 128) {
            int kk = idx & 31, n = idx >> 5;
            int k  = kb + kk;
            Bs[kk * 136 + n] = f2tf(k < DM ? W[(lc0 + n) * DM + k] : 0.0f);
        }
        __syncthreads();

        #pragma unroll
        for (int ks = 0; ks < 4; ks++) {
            const int k0 = ks * 8;
            unsigned a[2][4];
            #pragma unroll
            for (int i = 0; i < 2; i++) {
                int mb = wm0 + i * 16;
                a[i][0] = As[(k0 + tig) * 72 + mb + gid];
                a[i][1] = As[(k0 + tig) * 72 + mb + gid + 8];
                a[i][2] = As[(k0 + tig + 4) * 72 + mb + gid];
                a[i][3] = As[(k0 + tig + 4) * 72 + mb + gid + 8];
            }
            unsigned b[8][2];
            #pragma unroll
            for (int j = 0; j < 8; j++) {
                int nb = wn0 + j * 8;
                b[j][0] = Bs[(k0 + tig) * 136 + nb + gid];
                b[j][1] = Bs[(k0 + tig + 4) * 136 + nb + gid];
            }
            #pragma unroll
            for (int i = 0; i < 2; i++)
                #pragma unroll
                for (int j = 0; j < 8; j++)
                    mma_tf32(acc[i][j], a[i][0], a[i][1], a[i][2], a[i][3],
                             b[j][0], b[j][1]);
        }
    }

    const float scale = *cw;
    const float shift = *cb;

    #pragma unroll
    for (int i = 0; i < 2; i++) {
        #pragma unroll
        for (int j = 0; j < 8; j++) {
            const int colg = lc0 + wn0 + j * 8 + 2 * tig;
            const float b0v = bias[colg];
            const float b1v = bias[colg + 1];
            const int ns = colg >> 5;
            const int dk = colg & 31;

            int r0 = row0 + wm0 + i * 16 + gid;
            {
                int batch = r0 >> 1, l = r0 & 1;
                float2 v;
                v.x = fmaf(scale, acc[i][j][0] + b0v, shift);
                v.y = fmaf(scale, acc[i][j][1] + b1v, shift);
                *(float2*)&out[batch * 4096 + ns * 64 + l * 32 + dk] = v;
            }
            int r1 = r0 + 8;
            {
                int batch = r1 >> 1, l = r1 & 1;
                float2 v;
                v.x = fmaf(scale, acc[i][j][2] + b0v, shift);
                v.y = fmaf(scale, acc[i][j][3] + b1v, shift);
                *(float2*)&out[batch * 4096 + ns * 64 + l * 32 + dk] = v;
            }
        }
    }
}

// ---------------------------------------------------------------------------
// K2: attention. Products cached in registers across max/softmax passes.
// ---------------------------------------------------------------------------
__global__ void attn_kernel()
{
    __shared__ float sq[4][64], sk[4][64], sv[4][64];
    const int t   = threadIdx.x;
    const int sub = t >> 6;
    const int lt  = t & 63;
    const int b   = blockIdx.x * 4 + sub;
    const int batch = b >> 6;
    const int ns    = b & 63;
    const int base  = batch * 4096 + ns * 64;

    sq[sub][lt] = g_qkv[base + lt];
    sk[sub][lt] = g_qkv[2097152u + base + lt];
    sv[sub][lt] = g_qkv[2u * 2097152u + base + lt];
    __syncthreads();

    const int h = lt >> 1;
    const int w = lt & 1;
    const float q = sq[sub][lt];
    const float* Kv = sk[sub];
    const float* Vv = sv[sub];

    float e[32];
    #pragma unroll
    for (int g = 0; g < 32; g++)
        e[g] = (g == h) ? -1e30f : q * Kv[g * 2 + w];

    const float ew0 = q * Kv[h * 2 + 0];
    const float ew1 = q * Kv[h * 2 + 1];
    float m = fmaxf(ew0, ew1);
    #pragma unroll
    for (int g = 0; g < 32; g++) m = fmaxf(m, e[g]);

    float p0 = __expf(ew0 - m);
    float p1 = __expf(ew1 - m);
    float Z   = p0 + p1;
    float acc = p0 * Vv[h * 2 + 0] + p1 * Vv[h * 2 + 1];
    #pragma unroll
    for (int g = 0; g < 32; g++) {
        float pz = __expf(e[g] - m);
        Z   += pz;
        acc  = fmaf(pz, Vv[g * 2 + w], acc);
    }
    const float o = acc / Z;
    const int l  = lt >> 5;
    const int dk = lt & 31;
    g_att[(batch * 2 + l) * NSDK + ns * 32 + dk] = o;
}

// ---------------------------------------------------------------------------
// K3a: fc GEMM split-K partials (tf32). Block 32(M) x 112(N), 128 threads.
// grid (32 mtiles, 4 ksplits); each ksplit covers K=512.
// ---------------------------------------------------------------------------
__global__ __launch_bounds__(128) void fc_tc(const float* __restrict__ fcw)
{
    __shared__ unsigned As[32 * 40];
    __shared__ unsigned Bs[32 * 120];

    const int t    = threadIdx.x;
    const int lane = t & 31;
    const int wid  = t >> 5;
    const int tig  = lane & 3;
    const int gid  = lane >> 2;

    const int row0 = blockIdx.x * 32;
    const int ks   = blockIdx.y;

    const int wm0 = (wid >> 1) * 16;
    const int wn0 = (wid & 1) * 56;

    float acc[7][4] = {};

    for (int kc = 0; kc < 16; kc++) {
        const int kb = ks * 512 + kc * 32;
        __syncthreads();
        #pragma unroll
        for (int idx = t; idx < 1024; idx += 128) {
            int kk = idx & 31, m = idx >> 5;
            As[kk * 40 + m] = f2tf(g_att[(row0 + m) * NSDK + kb + kk]);
        }
        #pragma unroll
        for (int idx = t; idx < 3584; idx += 128) {
            int kk = idx & 31, n = idx >> 5;
            Bs[kk * 120 + n] = f2tf(n < DM ? fcw[n * NSDK + kb + kk] : 0.0f);
        }
        __syncthreads();

        #pragma unroll
        for (int kss = 0; kss < 4; kss++) {
            const int k0 = kss * 8;
            unsigned a0 = As[(k0 + tig) * 40 + wm0 + gid];
            unsigned a1 = As[(k0 + tig) * 40 + wm0 + gid + 8];
            unsigned a2 = As[(k0 + tig + 4) * 40 + wm0 + gid];
            unsigned a3 = As[(k0 + tig + 4) * 40 + wm0 + gid + 8];
            unsigned b[7][2];
            #pragma unroll
            for (int j = 0; j < 7; j++) {
                int nb = wn0 + j * 8;
                b[j][0] = Bs[(k0 + tig) * 120 + nb + gid];
                b[j][1] = Bs[(k0 + tig + 4) * 120 + nb + gid];
            }
            #pragma unroll
            for (int j = 0; j < 7; j++)
                mma_tf32(acc[j], a0, a1, a2, a3, b[j][0], b[j][1]);
        }
    }

    #pragma unroll
    for (int j = 0; j < 7; j++) {
        const int col = wn0 + j * 8 + 2 * tig;
        if (col < DM) {
            int r0 = row0 + wm0 + gid;
            *(float2*)&g_part[ks * PART_STRIDE + r0 * DM + col] =
                make_float2(acc[j][0], acc[j][1]);
            int r1 = r0 + 8;
            *(float2*)&g_part[ks * PART_STRIDE + r1 * DM + col] =
                make_float2(acc[j][2], acc[j][3]);
        }
    }
}

// ---------------------------------------------------------------------------
// K3b: reduce partials + bias + residual + LayerNorm1. Warp per row.
// ---------------------------------------------------------------------------
__global__ void ln1_kernel(const float* __restrict__ edges,
                           const float* __restrict__ fcb,
                           const float* __restrict__ g1,
                           const float* __restrict__ b1)
{
    const int wid  = threadIdx.x >> 5;
    const int lane = threadIdx.x & 31;
    const int row  = blockIdx.x * 8 + wid;

    float x[4];
    #pragma unroll
    for (int i = 0; i < 4; i++) {
        int c = lane + i * 32;
        float v = 0.0f;
        if (c < DM) {
            v = fcb[c] + edges[row * DM + c];
            #pragma unroll
            for (int s = 0; s < KSPLIT; s++)
                v += g_part[s * PART_STRIDE + row * DM + c];
        }
        x[i] = v;
    }

    float s = x[0] + x[1] + x[2] + x[3];
    #pragma unroll
    for (int off = 16; off > 0; off >>= 1) s += __shfl_xor_sync(0xffffffffu, s, off);
    const float mean = s * (1.0f / DM);

    float v2 = 0.0f;
    #pragma unroll
    for (int i = 0; i < 4; i++) {
        int c = lane + i * 32;
        if (c < DM) {
            float d = x[i] - mean;
            v2 = fmaf(d, d, v2);
        }
    }
    #pragma unroll
    for (int off = 16; off > 0; off >>= 1) v2 += __shfl_xor_sync(0xffffffffu, v2, off);
    const float inv = rsqrtf(v2 * (1.0f / DM) + 1e-5f);

    #pragma unroll
    for (int i = 0; i < 4; i++) {
        int c = lane + i * 32;
        if (c < DM)
            g_ln1[row * DM + c] = (x[i] - mean) * inv * g1[c] + b1[c];
    }
}

// ---------------------------------------------------------------------------
// K4a: MLP layer 1 GEMM (tf32): h[1024x400] = relu(ln1 @ w1^T + b1).
// Block 64(M) x 128(N), 128 threads. grid (4, 16).
// ---------------------------------------------------------------------------
__global__ __launch_bounds__(128) void mlp_l1_tc(const float* __restrict__ w1,
                                                 const float* __restrict__ b1)
{
    __shared__ unsigned As[32 * 72];
    __shared__ unsigned Bs[32 * 136];

    const int t    = threadIdx.x;
    const int lane = t & 31;
    const int wid  = t >> 5;
    const int tig  = lane & 3;
    const int gid  = lane >> 2;

    const int col0 = blockIdx.x * 128;    // 0..511, covers 400
    const int row0 = blockIdx.y * 64;

    const int wm0 = (wid >> 1) * 32;
    const int wn0 = (wid & 1) * 64;

    float acc[2][8][4] = {};

    for (int kc = 0; kc < 4; kc++) {
        const int kb = kc * 32;
        __syncthreads();
        #pragma unroll
        for (int idx = t; idx < 2048; idx += 128) {
            int kk = idx & 31, m = idx >> 5;
            int k  = kb + kk;
            As[kk * 72 + m] = f2tf(k < DM ? g_ln1[(row0 + m) * DM + k] : 0.0f);
        }
        #pragma unroll
        for (int idx = t; idx < 4096; idx += 128) {
            int kk = idx & 31, n = idx >> 5;
            int k  = kb + kk;
            int gc = col0 + n;
            Bs[kk * 136 + n] = f2tf((k < DM && gc < DI_) ? w1[gc * DM + k] : 0.0f);
        }
        __syncthreads();

        #pragma unroll
        for (int ks = 0; ks < 4; ks++) {
            const int k0 = ks * 8;
            unsigned a[2][4];
            #pragma unroll
            for (int i = 0; i < 2; i++) {
                int mb = wm0 + i * 16;
                a[i][0] = As[(k0 + tig) * 72 + mb + gid];
                a[i][1] = As[(k0 + tig) * 72 + mb + gid + 8];
                a[i][2] = As[(k0 + tig + 4) * 72 + mb + gid];
                a[i][3] = As[(k0 + tig + 4) * 72 + mb + gid + 8];
            }
            unsigned b[8][2];
            #pragma unroll
            for (int j = 0; j < 8; j++) {
                int nb = wn0 + j * 8;
                b[j][0] = Bs[(k0 + tig) * 136 + nb + gid];
                b[j][1] = Bs[(k0 + tig + 4) * 136 + nb + gid];
            }
            #pragma unroll
            for (int i = 0; i < 2; i++)
                #pragma unroll
                for (int j = 0; j < 8; j++)
                    mma_tf32(acc[i][j], a[i][0], a[i][1], a[i][2], a[i][3],
                             b[j][0], b[j][1]);
        }
    }

    #pragma unroll
    for (int i = 0; i < 2; i++) {
        #pragma unroll
        for (int j = 0; j < 8; j++) {
            const int colg = col0 + wn0 + j * 8 + 2 * tig;
            if (colg < DI_) {
                const float b0v = b1[colg];
                const float b1v = b1[colg + 1];
                int r0 = row0 + wm0 + i * 16 + gid;
                float2 v0, v1;
                v0.x = fmaxf(acc[i][j][0] + b0v, 0.0f);
                v0.y = fmaxf(acc[i][j][1] + b1v, 0.0f);
                v1.x = fmaxf(acc[i][j][2] + b0v, 0.0f);
                v1.y = fmaxf(acc[i][j][3] + b1v, 0.0f);
                *(float2*)&g_h[r0 * DI_ + colg]       = v0;
                *(float2*)&g_h[(r0 + 8) * DI_ + colg] = v1;
            }
        }
    }
}

// ---------------------------------------------------------------------------
// K4b: MLP layer 2 GEMM (tf32) + bias + residual + LayerNorm2 -> d_out.
// Block 32(M) x 112(N covers 100), K=400. grid 32. 128 threads.
// ---------------------------------------------------------------------------
__global__ __launch_bounds__(128) void mlp_l2_tc(const float* __restrict__ w2,
                                                 const float* __restrict__ b2,
                                                 const float* __restrict__ g2,
                                                 const float* __restrict__ bb2,
                                                 float* __restrict__ outp)
{
    __shared__ unsigned As[32 * 40];
    __shared__ unsigned Bs[32 * 120];
    __shared__ float    ys[32][113];

    const int t    = threadIdx.x;
    const int lane = t & 31;
    const int wid  = t >> 5;
    const int tig  = lane & 3;
    const int gid  = lane >> 2;

    const int row0 = blockIdx.x * 32;

    const int wm0 = (wid >> 1) * 16;
    const int wn0 = (wid & 1) * 56;

    float acc[7][4] = {};

    for (int kc = 0; kc < 13; kc++) {
        const int kb = kc * 32;
        __syncthreads();
        #pragma unroll
        for (int idx = t; idx < 1024; idx += 128) {
            int kk = idx & 31, m = idx >> 5;
            int k  = kb + kk;
            As[kk * 40 + m] = f2tf(k < DI_ ? g_h[(row0 + m) * DI_ + k] : 0.0f);
        }
        #pragma unroll
        for (int idx = t; idx < 3584; idx += 128) {
            int kk = idx & 31, n = idx >> 5;
            int k  = kb + kk;
            Bs[kk * 120 + n] = f2tf((n < DM && k < DI_) ? w2[n * DI_ + k] : 0.0f);
        }
        __syncthreads();

        #pragma unroll
        for (int kss = 0; kss < 4; kss++) {
            const int k0 = kss * 8;
            unsigned a0 = As[(k0 + tig) * 40 + wm0 + gid];
            unsigned a1 = As[(k0 + tig) * 40 + wm0 + gid + 8];
            unsigned a2 = As[(k0 + tig + 4) * 40 + wm0 + gid];
            unsigned a3 = As[(k0 + tig + 4) * 40 + wm0 + gid + 8];
            unsigned b[7][2];
            #pragma unroll
            for (int j = 0; j < 7; j++) {
                int nb = wn0 + j * 8;
                b[j][0] = Bs[(k0 + tig) * 120 + nb + gid];
                b[j][1] = Bs[(k0 + tig + 4) * 120 + nb + gid];
            }
            #pragma unroll
            for (int j = 0; j < 7; j++)
                mma_tf32(acc[j], a0, a1, a2, a3, b[j][0], b[j][1]);
        }
    }

    __syncthreads();
    #pragma unroll
    for (int j = 0; j < 7; j++) {
        const int col = wn0 + j * 8 + 2 * tig;
        const int r0  = wm0 + gid;
        ys[r0][col]         = acc[j][0];
        ys[r0][col + 1]     = acc[j][1];
        ys[r0 + 8][col]     = acc[j][2];
        ys[r0 + 8][col + 1] = acc[j][3];
    }
    __syncthreads();

    // LN2: 4 threads per row (quad), 25 cols each
    const int r    = t >> 2;
    const int s4   = t & 3;
    const int grow = row0 + r;

    float vals[25];
    float sum = 0.0f;
    #pragma unroll
    for (int j = 0; j < 25; j++) {
        int c = s4 + 4 * j;
        float v = ys[r][c] + b2[c] + g_ln1[grow * DM + c];
        vals[j] = v;
        sum += v;
    }
    sum += __shfl_xor_sync(0xffffffffu, sum, 1);
    sum += __shfl_xor_sync(0xffffffffu, sum, 2);
    const float mean = sum * (1.0f / DM);

    float v2 = 0.0f;
    #pragma unroll
    for (int j = 0; j < 25; j++) {
        float d = vals[j] - mean;
        v2 = fmaf(d, d, v2);
    }
    v2 += __shfl_xor_sync(0xffffffffu, v2, 1);
    v2 += __shfl_xor_sync(0xffffffffu, v2, 2);
    const float inv = rsqrtf(v2 * (1.0f / DM) + 1e-5f);

    #pragma unroll
    for (int j = 0; j < 25; j++) {
        int c = s4 + 4 * j;
        outp[grow * DM + c] = (vals[j] - mean) * inv * g2[c] + bb2[c];
    }
}

// ---------------------------------------------------------------------------
extern "C" void kernel_launch(void* const* d_in, const int* in_sizes, int n_in,
                              void* d_out, int out_size)
{
    (void)in_sizes; (void)n_in; (void)out_size;
    const float* edges = (const float*)d_in[0];
    const float* wq    = (const float*)d_in[1];
    const float* bq    = (const float*)d_in[2];
    const float* wk    = (const float*)d_in[3];
    const float* bk    = (const float*)d_in[4];
    const float* wv    = (const float*)d_in[5];
    const float* bv    = (const float*)d_in[6];
    const float* qcw   = (const float*)d_in[7];
    const float* qcb   = (const float*)d_in[8];
    const float* kcw   = (const float*)d_in[9];
    const float* kcb   = (const float*)d_in[10];
    const float* vcw   = (const float*)d_in[11];
    const float* vcb   = (const float*)d_in[12];
    const float* fcw   = (const float*)d_in[13];
    const float* fcb   = (const float*)d_in[14];
    const float* ln1g  = (const float*)d_in[15];
    const float* ln1b  = (const float*)d_in[16];
    const float* w1w   = (const float*)d_in[17];
    const float* w1b   = (const float*)d_in[18];
    const float* w2w   = (const float*)d_in[19];
    const float* w2b   = (const float*)d_in[20];
    const float* ln2g  = (const float*)d_in[21];
    const float* ln2b  = (const float*)d_in[22];

    qkv_tc<<<dim3(48, 16), 128>>>(edges, wq, bq, wk, bk, wv, bv,
                                  qcw, qcb, kcw, kcb, vcw, vcb);
    attn_kernel<<<NBLK / 4, 256>>>();
    fc_tc<<<dim3(32, KSPLIT), 128>>>(fcw);
    ln1_kernel<<<ROWS / 8, 256>>>(edges, fcb, ln1g, ln1b);
    mlp_l1_tc<<<dim3(4, 16), 128>>>(w1w, w1b);
    mlp_l2_tc<<<32, 128>>>(w2w, w2b, ln2g, ln2b, (float*)d_out);
}